// round 1
// baseline (speedup 1.0000x reference)
#include <cuda_runtime.h>
#include <cuda_bf16.h>

// ---------------- problem constants (fixed by setup_inputs) ----------------
#define BATCH   32
#define NNODE   512
#define NROWS   (BATCH*NNODE)      // 16384
#define FDIM    1024
#define H1      512
#define H2      256
#define H3      128
#define NC      8
#define EDGES   32768              // per batch
#define NEDGE   (BATCH*EDGES)      // 1048576
#define EH      64
#define EC      10
#define CATTR   9
#define NODE_OUT_ELEMS (NROWS*NC)  // 131072

// ---------------- scratch (device globals; no allocation allowed) ----------
__device__ float g_h1[NROWS * H1];   // 32 MB
__device__ float g_h2[NROWS * H2];   // 16 MB
__device__ float g_h3[NROWS * H3];   //  8 MB

// ---------------- fused GEMM + (BN)+ReLU epilogue ---------------------------
// C[M,N] = relu( (A[M,K] @ W[K,N] + bias) [*bn_scale + bn_shift] )
// EPI==1: apply folded batchnorm.  EPI==0: bias+relu only.
// Requires M%128==0, N%128==0, K%8==0 (true for all three uses).
template<int M, int N, int K, int EPI>
__global__ __launch_bounds__(256)
void gemm_relu_kernel(const float* __restrict__ A,
                      const float* __restrict__ W,
                      const float* __restrict__ bias,
                      const float* __restrict__ bng,
                      const float* __restrict__ bnb,
                      const float* __restrict__ bnrm,
                      const float* __restrict__ bnrv,
                      float* __restrict__ C)
{
    constexpr int BM = 128, BN = 128, BK = 8;
    __shared__ float As[BK][BM];
    __shared__ float Bs[BK][BN];

    const int bm = blockIdx.y, bn = blockIdx.x;
    const int tid = threadIdx.x;
    const int tx = tid % 16;          // 16 cols of threads
    const int ty = tid / 16;          // 16 rows of threads

    // loaders
    const int a_row = tid >> 1;             // 0..127
    const int a_kc  = (tid & 1) * 4;        // 0 or 4
    const int b_kr  = tid >> 5;             // 0..7
    const int b_col = (tid & 31) * 4;       // 0..124

    float acc[8][8];
    #pragma unroll
    for (int i = 0; i < 8; i++)
        #pragma unroll
        for (int j = 0; j < 8; j++) acc[i][j] = 0.f;

    const float* Ap = A + (size_t)(bm * BM + a_row) * K + a_kc;
    const float* Wp = W + (size_t)b_kr * N + bn * BN + b_col;

    for (int kt = 0; kt < K; kt += BK) {
        float4 av = *(const float4*)(Ap + kt);
        As[a_kc + 0][a_row] = av.x;
        As[a_kc + 1][a_row] = av.y;
        As[a_kc + 2][a_row] = av.z;
        As[a_kc + 3][a_row] = av.w;
        float4 bv = *(const float4*)(Wp + (size_t)kt * N);
        *(float4*)&Bs[b_kr][b_col] = bv;
        __syncthreads();

        #pragma unroll
        for (int k = 0; k < BK; k++) {
            float am[8], wn[8];
            *(float4*)&am[0] = *(const float4*)&As[k][ty * 8];
            *(float4*)&am[4] = *(const float4*)&As[k][ty * 8 + 4];
            *(float4*)&wn[0] = *(const float4*)&Bs[k][tx * 8];
            *(float4*)&wn[4] = *(const float4*)&Bs[k][tx * 8 + 4];
            #pragma unroll
            for (int i = 0; i < 8; i++)
                #pragma unroll
                for (int j = 0; j < 8; j++)
                    acc[i][j] += am[i] * wn[j];
        }
        __syncthreads();
    }

    // epilogue: fold BN into per-column scale/shift
    float bb[8], sc[8], sh[8];
    #pragma unroll
    for (int j = 0; j < 8; j++) {
        int col = bn * BN + tx * 8 + j;
        bb[j] = bias[col];
        if (EPI == 1) {
            float s = bng[col] * rsqrtf(bnrv[col] + 1e-5f);
            sc[j] = s;
            sh[j] = bnb[col] - bnrm[col] * s;
        }
    }
    #pragma unroll
    for (int i = 0; i < 8; i++) {
        int row = bm * BM + ty * 8 + i;
        float v[8];
        #pragma unroll
        for (int j = 0; j < 8; j++) {
            float t = acc[i][j] + bb[j];
            if (EPI == 1) t = t * sc[j] + sh[j];
            v[j] = fmaxf(t, 0.f);
        }
        float* cp = C + (size_t)row * N + bn * BN + tx * 8;
        *(float4*)(cp + 0) = make_float4(v[0], v[1], v[2], v[3]);
        *(float4*)(cp + 4) = make_float4(v[4], v[5], v[6], v[7]);
    }
}

// ---------------- node head: h3(16384x128) @ ni_w(128x8) -> sigmoid --------
__global__ __launch_bounds__(256)
void node_out_kernel(const float* __restrict__ h3,
                     const float* __restrict__ w,   // (128,8) row-major
                     const float* __restrict__ b,   // (8)
                     float* __restrict__ out)       // (16384*8)
{
    int t = blockIdx.x * 256 + threadIdx.x;     // 0..131071
    int row = t >> 3;
    int j = t & 7;
    const float* x = h3 + (size_t)row * H3;
    float acc = b[j];
    #pragma unroll 8
    for (int k = 0; k < H3; k++)
        acc += x[k] * __ldg(&w[k * NC + j]);
    out[t] = 1.f / (1.f + __expf(-acc));
}

// ---------------- fused edge MLP: gather + 18->64->64->10 + sigmoid --------
__global__ __launch_bounds__(256)
void edge_kernel(const float* __restrict__ bboxes,   // (B,N,4)
                 const float* __restrict__ dirs,     // (B,N,4)
                 const float* __restrict__ prio,     // (B,N)
                 const int*   __restrict__ eidx,     // (B,2,E)
                 const float* __restrict__ w1, const float* __restrict__ b1, // (18,64),(64)
                 const float* __restrict__ w2, const float* __restrict__ b2, // (64,64),(64)
                 const float* __restrict__ wi, const float* __restrict__ bi, // (64,10),(10)
                 float* __restrict__ out)            // (NEDGE*10) at offset already applied
{
    __shared__ float sw1[2 * CATTR * EH];   // 18*64
    __shared__ float sw2[EH * EH];          // 64*64
    __shared__ float swi[EH * 12];          // 64 x 10 padded to 12
    __shared__ float sb1[EH], sb2[EH], sbi[12];

    for (int i = threadIdx.x; i < 2 * CATTR * EH; i += 256) sw1[i] = w1[i];
    for (int i = threadIdx.x; i < EH * EH;        i += 256) sw2[i] = w2[i];
    for (int i = threadIdx.x; i < EH * 12;        i += 256) {
        int k = i / 12, j = i % 12;
        swi[i] = (j < EC) ? wi[k * EC + j] : 0.f;
    }
    for (int i = threadIdx.x; i < EH; i += 256) { sb1[i] = b1[i]; sb2[i] = b2[i]; }
    if (threadIdx.x < 12) sbi[threadIdx.x] = (threadIdx.x < EC) ? bi[threadIdx.x] : 0.f;
    __syncthreads();

    const int e  = blockIdx.x * 256 + threadIdx.x;  // 0..NEDGE-1
    const int bt = e >> 15;                          // batch
    const int ei = e & (EDGES - 1);
    const int src = eidx[bt * 2 * EDGES + ei];
    const int dst = eidx[bt * 2 * EDGES + EDGES + ei];

    float x[2 * CATTR];
    {
        int n0 = bt * NNODE + src;
        float4 bb = *(const float4*)&bboxes[(size_t)n0 * 4];
        float4 dd = *(const float4*)&dirs[(size_t)n0 * 4];
        const float inv = 1.f / 1024.f;
        x[0] = bb.x * inv; x[1] = bb.y * inv; x[2] = bb.z * inv; x[3] = bb.w * inv;
        x[4] = dd.x; x[5] = dd.y; x[6] = dd.z; x[7] = dd.w;
        x[8] = prio[n0];
        int n1 = bt * NNODE + dst;
        float4 bb2 = *(const float4*)&bboxes[(size_t)n1 * 4];
        float4 dd2 = *(const float4*)&dirs[(size_t)n1 * 4];
        x[9]  = bb2.x * inv; x[10] = bb2.y * inv; x[11] = bb2.z * inv; x[12] = bb2.w * inv;
        x[13] = dd2.x; x[14] = dd2.y; x[15] = dd2.z; x[16] = dd2.w;
        x[17] = prio[n1];
    }

    // layer 1: 18 -> 64
    float h[EH];
    #pragma unroll
    for (int j = 0; j < EH; j += 4) *(float4*)&h[j] = *(const float4*)&sb1[j];
    #pragma unroll
    for (int k = 0; k < 2 * CATTR; k++) {
        float xk = x[k];
        const float4* wr = (const float4*)&sw1[k * EH];
        #pragma unroll
        for (int j4 = 0; j4 < EH / 4; j4++) {
            float4 wv = wr[j4];
            h[j4 * 4 + 0] += xk * wv.x;
            h[j4 * 4 + 1] += xk * wv.y;
            h[j4 * 4 + 2] += xk * wv.z;
            h[j4 * 4 + 3] += xk * wv.w;
        }
    }

    // layer 2: 64 -> 64 (relu on h applied when consumed)
    float g[EH];
    #pragma unroll
    for (int j = 0; j < EH; j += 4) *(float4*)&g[j] = *(const float4*)&sb2[j];
    #pragma unroll
    for (int k = 0; k < EH; k++) {
        float hk = fmaxf(h[k], 0.f);
        const float4* wr = (const float4*)&sw2[k * EH];
        #pragma unroll
        for (int j4 = 0; j4 < EH / 4; j4++) {
            float4 wv = wr[j4];
            g[j4 * 4 + 0] += hk * wv.x;
            g[j4 * 4 + 1] += hk * wv.y;
            g[j4 * 4 + 2] += hk * wv.z;
            g[j4 * 4 + 3] += hk * wv.w;
        }
    }

    // layer 3: 64 -> 10 (padded to 12) + sigmoid
    float acc[12];
    #pragma unroll
    for (int j = 0; j < 12; j += 4) *(float4*)&acc[j] = *(const float4*)&sbi[j];
    #pragma unroll
    for (int k = 0; k < EH; k++) {
        float gk = fmaxf(g[k], 0.f);
        const float4* wr = (const float4*)&swi[k * 12];
        #pragma unroll
        for (int j4 = 0; j4 < 3; j4++) {
            float4 wv = wr[j4];
            acc[j4 * 4 + 0] += gk * wv.x;
            acc[j4 * 4 + 1] += gk * wv.y;
            acc[j4 * 4 + 2] += gk * wv.z;
            acc[j4 * 4 + 3] += gk * wv.w;
        }
    }
    float* op = out + (size_t)e * EC;
    #pragma unroll
    for (int j = 0; j < EC; j++)
        op[j] = 1.f / (1.f + __expf(-acc[j]));
}

// ---------------- launch ----------------------------------------------------
extern "C" void kernel_launch(void* const* d_in, const int* in_sizes, int n_in,
                              void* d_out, int out_size)
{
    const float* roi    = (const float*)d_in[0];
    const float* bboxes = (const float*)d_in[1];
    const float* dirs   = (const float*)d_in[2];
    const float* prio   = (const float*)d_in[3];
    const int*   eidx   = (const int*)  d_in[4];
    const float* np_w1  = (const float*)d_in[5];
    const float* np_b1  = (const float*)d_in[6];
    const float* bn1_g  = (const float*)d_in[7];
    const float* bn1_b  = (const float*)d_in[8];
    const float* bn1_rm = (const float*)d_in[9];
    const float* bn1_rv = (const float*)d_in[10];
    const float* np_w2  = (const float*)d_in[11];
    const float* np_b2  = (const float*)d_in[12];
    const float* bn2_g  = (const float*)d_in[13];
    const float* bn2_b  = (const float*)d_in[14];
    const float* bn2_rm = (const float*)d_in[15];
    const float* bn2_rv = (const float*)d_in[16];
    const float* np_w3  = (const float*)d_in[17];
    const float* np_b3  = (const float*)d_in[18];
    const float* ni_w   = (const float*)d_in[19];
    const float* ni_b   = (const float*)d_in[20];
    const float* ep_w1  = (const float*)d_in[21];
    const float* ep_b1  = (const float*)d_in[22];
    const float* ep_w2  = (const float*)d_in[23];
    const float* ep_b2  = (const float*)d_in[24];
    const float* ei_w   = (const float*)d_in[25];
    const float* ei_b   = (const float*)d_in[26];

    float* out = (float*)d_out;

    float *h1, *h2, *h3;
    cudaGetSymbolAddress((void**)&h1, g_h1);
    cudaGetSymbolAddress((void**)&h2, g_h2);
    cudaGetSymbolAddress((void**)&h3, g_h3);

    // Edge path (independent of node GEMM chain) — launch first.
    edge_kernel<<<NEDGE / 256, 256>>>(bboxes, dirs, prio, eidx,
                                      ep_w1, ep_b1, ep_w2, ep_b2, ei_w, ei_b,
                                      out + NODE_OUT_ELEMS);

    // Node MLP chain.
    {
        dim3 grid(H1 / 128, NROWS / 128);
        gemm_relu_kernel<NROWS, H1, FDIM, 1><<<grid, 256>>>(
            roi, np_w1, np_b1, bn1_g, bn1_b, bn1_rm, bn1_rv, h1);
    }
    {
        dim3 grid(H2 / 128, NROWS / 128);
        gemm_relu_kernel<NROWS, H2, H1, 1><<<grid, 256>>>(
            h1, np_w2, np_b2, bn2_g, bn2_b, bn2_rm, bn2_rv, h2);
    }
    {
        dim3 grid(H3 / 128, NROWS / 128);
        gemm_relu_kernel<NROWS, H3, H2, 0><<<grid, 256>>>(
            h2, np_w3, np_b3, nullptr, nullptr, nullptr, nullptr, h3);
    }
    node_out_kernel<<<NODE_OUT_ELEMS / 256, 256>>>(h3, ni_w, ni_b, out);
}